// round 8
// baseline (speedup 1.0000x reference)
#include <cuda_runtime.h>
#include <cuda_bf16.h>

#define NMAX 4096
#define BIGF 1e30f
#define TILE 128
#define NTMAX (NMAX / TILE)   // 32

// Partial-min buffers (no init needed: every valid entry is written each run)
__device__ float g_pcol[NTMAX][NMAX];  // [itile][j]: min over rows of itile, col j (+row pen)
__device__ float g_prow[NTMAX][NMAX];  // [jtile][i]: min over cols of jtile, row i (+col pen)

// ---------------------------------------------------------------------------
// Dist kernel: inline prep + tiled masked-min with dot-product expansion.
// 128x128 tile / block, 256 threads (16x16), 8x8 register micro-tile.
// D = rr + cc - 2*dot. u = dot + ci (ci=-0.5cc):
//   col candidate: fma(u,-2, rr+rp);  row candidate: fma(u,-2, cp) (+rr after)
// Block-level combine via smem atomics; block result -> plain STG to partials.
// ---------------------------------------------------------------------------
__global__ void __launch_bounds__(256) dist_kernel(const float* __restrict__ norm,
                                                   const float* __restrict__ pts,
                                                   int n) {
    __shared__ float4 srow[TILE];         // hx, hy, hz, rr
    __shared__ float  srowA[TILE];        // rr + rowPenalty
    __shared__ float4 scol[TILE];         // cx, cy, cz, ci (= -0.5*cc)
    __shared__ float  scolP[TILE];        // colPenalty
    __shared__ unsigned int credu[TILE];
    __shared__ unsigned int rredu[TILE];

    int t = threadIdx.x;
    int i0 = blockIdx.y * TILE;
    int j0 = blockIdx.x * TILE;

    float nx = __ldg(norm), ny = __ldg(norm + 1), nz = __ldg(norm + 2), dd = __ldg(norm + 3);
    float nn = nx * nx + ny * ny + nz * nz;

    if (t < TILE) {                       // rows: reflected points
        int gi = i0 + t;
        float4 v = make_float4(0.f, 0.f, 0.f, 0.f);
        float A = BIGF;
        if (gi < n) {
            float px = pts[3 * gi], py = pts[3 * gi + 1], pz = pts[3 * gi + 2];
            float ts = -2.0f * (px * nx + py * ny + pz * nz + dd);
            float k = ts / nn;
            float hx = fmaf(k, nx, px), hy = fmaf(k, ny, py), hz = fmaf(k, nz, pz);
            float rr = fmaf(hx, hx, fmaf(hy, hy, hz * hz));
            v = make_float4(hx, hy, hz, rr);
            A = rr + (ts > 0.0f ? 0.0f : BIGF);
        }
        srow[t] = v;
        srowA[t] = A;
        credu[t] = __float_as_uint(BIGF);
    } else {                              // cols: original points
        int u = t - TILE;
        int gj = j0 + u;
        float4 v = make_float4(0.f, 0.f, 0.f, 0.f);
        float P = BIGF;
        if (gj < n) {
            float px = pts[3 * gj], py = pts[3 * gj + 1], pz = pts[3 * gj + 2];
            float ts = -2.0f * (px * nx + py * ny + pz * nz + dd);
            float cc = fmaf(px, px, fmaf(py, py, pz * pz));
            v = make_float4(px, py, pz, -0.5f * cc);
            P = (ts > 0.0f ? BIGF : 0.0f);
        }
        scol[u] = v;
        scolP[u] = P;
        rredu[u] = __float_as_uint(BIGF);
    }
    __syncthreads();

    int tx = t & 15, ty = t >> 4;

    float RX[8], RY[8], RZ[8], RA[8], RR[8];
#pragma unroll
    for (int r = 0; r < 8; r++) {
        float4 v = srow[ty * 8 + r];
        RX[r] = v.x; RY[r] = v.y; RZ[r] = v.z; RR[r] = v.w;
        RA[r] = srowA[ty * 8 + r];
    }
    float CX[8], CY[8], CZ[8], CI[8], CP[8];
#pragma unroll
    for (int c = 0; c < 8; c++) {
        float4 v = scol[c * 16 + tx];     // consecutive tx -> conflict-free
        CX[c] = v.x; CY[c] = v.y; CZ[c] = v.z; CI[c] = v.w;
        CP[c] = scolP[c * 16 + tx];
    }

    float cmin[8], rmin[8];
#pragma unroll
    for (int k = 0; k < 8; k++) { cmin[k] = BIGF; rmin[k] = BIGF; }

#pragma unroll
    for (int r = 0; r < 8; r++) {
        float rxv = RX[r], ryv = RY[r], rzv = RZ[r], Av = RA[r];
        float rm = rmin[r];
#pragma unroll
        for (int c = 0; c < 8; c++) {
            float u = fmaf(rzv, CZ[c], fmaf(ryv, CY[c], fmaf(rxv, CX[c], CI[c])));
            cmin[c] = fminf(cmin[c], fmaf(u, -2.0f, Av));
            rm      = fminf(rm,      fmaf(u, -2.0f, CP[c]));
        }
        rmin[r] = rm;
    }

    // block-level combine (uint order valid: all candidates clamped >= 0 on write)
#pragma unroll
    for (int c = 0; c < 8; c++)
        atomicMin(&credu[c * 16 + tx], __float_as_uint(fmaxf(cmin[c], 0.0f)));
#pragma unroll
    for (int r = 0; r < 8; r++) {
        float v = fmaxf(rmin[r] + RR[r], 0.0f);
        atomicMin(&rredu[ty * 8 + r], __float_as_uint(v));
    }
    __syncthreads();

    // plain stores to partial buffers (unique addresses; no init, no atomics)
    if (t < TILE) {
        int gj = j0 + t;
        if (gj < n) g_pcol[blockIdx.y][gj] = __uint_as_float(credu[t]);
    } else {
        int u = t - TILE;
        int gi = i0 + u;
        if (gi < n) g_prow[blockIdx.x][gi] = __uint_as_float(rredu[u]);
    }
}

// ---------------------------------------------------------------------------
// Reduce: combine partials (32 tiles) + masked means + scalar. 1024 threads.
// Loads are coalesced (threads own contiguous j) and independent (high MLP).
// ---------------------------------------------------------------------------
__global__ void __launch_bounds__(1024) reduce_kernel(const float* __restrict__ norm,
                                                      const float* __restrict__ pts,
                                                      float* __restrict__ out,
                                                      int n, int ntiles) {
    int t = threadIdx.x;
    float nx = __ldg(norm), ny = __ldg(norm + 1), nz = __ldg(norm + 2), dd = __ldg(norm + 3);
    float s1 = 0.f, s2 = 0.f, c1 = 0.f, c2 = 0.f;

    for (int i = t; i < n; i += 1024) {
        float d1v = BIGF, d2v = BIGF;
#pragma unroll 8
        for (int k = 0; k < ntiles; k++) {
            d1v = fminf(d1v, g_pcol[k][i]);
            d2v = fminf(d2v, g_prow[k][i]);
        }
        float px = __ldg(pts + 3 * i), py = __ldg(pts + 3 * i + 1), pz = __ldg(pts + 3 * i + 2);
        float ts = -2.0f * (px * nx + py * ny + pz * nz + dd);
        if (ts > 0.0f) { s2 += d2v; c1 += 1.0f; }   // m1 rows -> av2 terms
        else           { s1 += d1v; c2 += 1.0f; }   // m2 cols -> av1 terms
    }
#pragma unroll
    for (int o = 16; o > 0; o >>= 1) {
        s1 += __shfl_xor_sync(0xffffffffu, s1, o);
        s2 += __shfl_xor_sync(0xffffffffu, s2, o);
        c1 += __shfl_xor_sync(0xffffffffu, c1, o);
        c2 += __shfl_xor_sync(0xffffffffu, c2, o);
    }
    __shared__ float sh[4][32];
    int w = t >> 5, l = t & 31;
    if (l == 0) { sh[0][w] = s1; sh[1][w] = s2; sh[2][w] = c1; sh[3][w] = c2; }
    __syncthreads();
    if (w == 0) {
        float a = sh[0][l], b = sh[1][l], c = sh[2][l], d = sh[3][l];
#pragma unroll
        for (int o = 16; o > 0; o >>= 1) {
            a += __shfl_xor_sync(0xffffffffu, a, o);
            b += __shfl_xor_sync(0xffffffffu, b, o);
            c += __shfl_xor_sync(0xffffffffu, c, o);
            d += __shfl_xor_sync(0xffffffffu, d, o);
        }
        if (l == 0) {
            c = fmaxf(c, 1.0f);   // C1
            d = fmaxf(d, 1.0f);   // C2
            out[0] = (0.5f * (a / d) + 0.5f * (b / c)) * 100.0f;
        }
    }
}

// ---------------------------------------------------------------------------
extern "C" void kernel_launch(void* const* d_in, const int* in_sizes, int n_in,
                              void* d_out, int out_size) {
    const float* a0 = (const float*)d_in[0];
    const float* a1 = (const float*)d_in[1];
    const float* norm;
    const float* pts;
    int n;
    if (in_sizes[0] == 4) { norm = a0; pts = a1; n = in_sizes[1] / 3; }
    else                  { norm = a1; pts = a0; n = in_sizes[0] / 3; }

    float* out = (float*)d_out;

    int nt = (n + TILE - 1) / TILE;
    dim3 grid(nt, nt);
    dist_kernel<<<grid, 256>>>(norm, pts, n);

    reduce_kernel<<<1, 1024>>>(norm, pts, out, n, nt);
}

// round 9
// speedup vs baseline: 1.5805x; 1.5805x over previous
#include <cuda_runtime.h>
#include <cuda_bf16.h>

#define NMAX 4096
#define BIGF 1e30f
#define TILE 128

// Scratch (__device__ globals; allocation is forbidden)
__device__ unsigned int g_d1[NMAX];   // min over m1 rows, per column j (float bits)
__device__ unsigned int g_d2[NMAX];   // min over m2 cols, per row i    (float bits)

// ---------------------------------------------------------------------------
// Dist kernel (R5-proven): inline prep + tiled masked-min, dot expansion.
// 128x128 tile / block, 256 threads (16x16), 8x8 register micro-tile.
// D = rr + cc - 2*dot. u = dot + ci (ci=-0.5cc):
//   col candidate: fma(u,-2, rr+rp);  row candidate: fma(u,-2, cp) (+rr after)
// => 5 FFMA + 2 FMNMX per pair. Block combine via smem atomicMin (bit order
// valid: candidates clamped >= 0), then one global atomicMin per line.
// ---------------------------------------------------------------------------
__global__ void __launch_bounds__(256) dist_kernel(const float* __restrict__ norm,
                                                   const float* __restrict__ pts,
                                                   int n) {
    __shared__ float4 srow[TILE];         // hx, hy, hz, rr
    __shared__ float  srowA[TILE];        // rr + rowPenalty
    __shared__ float4 scol[TILE];         // cx, cy, cz, ci (= -0.5*cc)
    __shared__ float  scolP[TILE];        // colPenalty
    __shared__ unsigned int credu[TILE];
    __shared__ unsigned int rredu[TILE];

    int t = threadIdx.x;
    int i0 = blockIdx.y * TILE;
    int j0 = blockIdx.x * TILE;

    float nx = __ldg(norm), ny = __ldg(norm + 1), nz = __ldg(norm + 2), dd = __ldg(norm + 3);
    float nn = nx * nx + ny * ny + nz * nz;

    if (t < TILE) {                       // rows: reflected points
        int gi = i0 + t;
        float4 v = make_float4(0.f, 0.f, 0.f, 0.f);
        float A = BIGF;
        if (gi < n) {
            float px = pts[3 * gi], py = pts[3 * gi + 1], pz = pts[3 * gi + 2];
            float ts = -2.0f * (px * nx + py * ny + pz * nz + dd);
            float k = ts / nn;
            float hx = fmaf(k, nx, px), hy = fmaf(k, ny, py), hz = fmaf(k, nz, pz);
            float rr = fmaf(hx, hx, fmaf(hy, hy, hz * hz));
            v = make_float4(hx, hy, hz, rr);
            A = rr + (ts > 0.0f ? 0.0f : BIGF);
        }
        srow[t] = v;
        srowA[t] = A;
        credu[t] = __float_as_uint(BIGF);
    } else {                              // cols: original points
        int u = t - TILE;
        int gj = j0 + u;
        float4 v = make_float4(0.f, 0.f, 0.f, 0.f);
        float P = BIGF;
        if (gj < n) {
            float px = pts[3 * gj], py = pts[3 * gj + 1], pz = pts[3 * gj + 2];
            float ts = -2.0f * (px * nx + py * ny + pz * nz + dd);
            float cc = fmaf(px, px, fmaf(py, py, pz * pz));
            v = make_float4(px, py, pz, -0.5f * cc);
            P = (ts > 0.0f ? BIGF : 0.0f);
        }
        scol[u] = v;
        scolP[u] = P;
        rredu[u] = __float_as_uint(BIGF);
    }
    __syncthreads();

    int tx = t & 15, ty = t >> 4;

    float RX[8], RY[8], RZ[8], RA[8], RR[8];
#pragma unroll
    for (int r = 0; r < 8; r++) {
        float4 v = srow[ty * 8 + r];
        RX[r] = v.x; RY[r] = v.y; RZ[r] = v.z; RR[r] = v.w;
        RA[r] = srowA[ty * 8 + r];
    }
    float CX[8], CY[8], CZ[8], CI[8], CP[8];
#pragma unroll
    for (int c = 0; c < 8; c++) {
        float4 v = scol[c * 16 + tx];     // consecutive tx -> conflict-free
        CX[c] = v.x; CY[c] = v.y; CZ[c] = v.z; CI[c] = v.w;
        CP[c] = scolP[c * 16 + tx];
    }

    float cmin[8], rmin[8];
#pragma unroll
    for (int k = 0; k < 8; k++) { cmin[k] = BIGF; rmin[k] = BIGF; }

#pragma unroll
    for (int r = 0; r < 8; r++) {
        float rxv = RX[r], ryv = RY[r], rzv = RZ[r], Av = RA[r];
        float rm = rmin[r];
#pragma unroll
        for (int c = 0; c < 8; c++) {
            float u = fmaf(rzv, CZ[c], fmaf(ryv, CY[c], fmaf(rxv, CX[c], CI[c])));
            cmin[c] = fminf(cmin[c], fmaf(u, -2.0f, Av));
            rm      = fminf(rm,      fmaf(u, -2.0f, CP[c]));
        }
        rmin[r] = rm;
    }

    // block-level combine (clamped >= 0 so uint order == float order)
#pragma unroll
    for (int c = 0; c < 8; c++)
        atomicMin(&credu[c * 16 + tx], __float_as_uint(fmaxf(cmin[c], 0.0f)));
#pragma unroll
    for (int r = 0; r < 8; r++) {
        float v = fmaxf(rmin[r] + RR[r], 0.0f);
        atomicMin(&rredu[ty * 8 + r], __float_as_uint(v));
    }
    __syncthreads();

    if (t < TILE) {
        int gj = j0 + t;
        if (gj < n) atomicMin(&g_d1[gj], credu[t]);
    } else {
        int u = t - TILE;
        int gi = i0 + u;
        if (gi < n) atomicMin(&g_d2[gi], rredu[u]);
    }
}

// ---------------------------------------------------------------------------
// Reduce: 1024 threads, each owns 4 consecutive points. Vectorized loads
// (uint4 for mins, float4 x3 for points) -> few, wide, independent requests.
// ---------------------------------------------------------------------------
__global__ void __launch_bounds__(1024) reduce_kernel(const float* __restrict__ norm,
                                                      const float* __restrict__ pts,
                                                      float* __restrict__ out, int n) {
    int t = threadIdx.x;
    float nx = __ldg(norm), ny = __ldg(norm + 1), nz = __ldg(norm + 2), dd = __ldg(norm + 3);
    float s1 = 0.f, s2 = 0.f, c1 = 0.f, c2 = 0.f;

    for (int base = t * 4; base < n; base += 1024 * 4) {
        if (base + 3 < n && ((base & 3) == 0)) {
            uint4 u1 = *reinterpret_cast<const uint4*>(&g_d1[base]);
            uint4 u2 = *reinterpret_cast<const uint4*>(&g_d2[base]);
            float4 pA = *reinterpret_cast<const float4*>(pts + 3 * base);       // x0 y0 z0 x1
            float4 pB = *reinterpret_cast<const float4*>(pts + 3 * base + 4);   // y1 z1 x2 y2
            float4 pC = *reinterpret_cast<const float4*>(pts + 3 * base + 8);   // z2 x3 y3 z3
            float d1v[4] = {__uint_as_float(u1.x), __uint_as_float(u1.y),
                            __uint_as_float(u1.z), __uint_as_float(u1.w)};
            float d2v[4] = {__uint_as_float(u2.x), __uint_as_float(u2.y),
                            __uint_as_float(u2.z), __uint_as_float(u2.w)};
            float X[4] = {pA.x, pA.w, pB.z, pC.y};
            float Y[4] = {pA.y, pB.x, pB.w, pC.z};
            float Z[4] = {pA.z, pB.y, pC.x, pC.w};
#pragma unroll
            for (int q = 0; q < 4; q++) {
                float ts = -2.0f * (X[q] * nx + Y[q] * ny + Z[q] * nz + dd);
                if (ts > 0.0f) { s2 += d2v[q]; c1 += 1.0f; }
                else           { s1 += d1v[q]; c2 += 1.0f; }
            }
        } else {
            for (int i = base; i < n && i < base + 4; i++) {
                float px = pts[3 * i], py = pts[3 * i + 1], pz = pts[3 * i + 2];
                float ts = -2.0f * (px * nx + py * ny + pz * nz + dd);
                if (ts > 0.0f) { s2 += __uint_as_float(g_d2[i]); c1 += 1.0f; }
                else           { s1 += __uint_as_float(g_d1[i]); c2 += 1.0f; }
            }
        }
    }
#pragma unroll
    for (int o = 16; o > 0; o >>= 1) {
        s1 += __shfl_xor_sync(0xffffffffu, s1, o);
        s2 += __shfl_xor_sync(0xffffffffu, s2, o);
        c1 += __shfl_xor_sync(0xffffffffu, c1, o);
        c2 += __shfl_xor_sync(0xffffffffu, c2, o);
    }
    __shared__ float sh[4][32];
    int w = t >> 5, l = t & 31;
    if (l == 0) { sh[0][w] = s1; sh[1][w] = s2; sh[2][w] = c1; sh[3][w] = c2; }
    __syncthreads();
    if (w == 0) {
        float a = sh[0][l], b = sh[1][l], c = sh[2][l], d = sh[3][l];
#pragma unroll
        for (int o = 16; o > 0; o >>= 1) {
            a += __shfl_xor_sync(0xffffffffu, a, o);
            b += __shfl_xor_sync(0xffffffffu, b, o);
            c += __shfl_xor_sync(0xffffffffu, c, o);
            d += __shfl_xor_sync(0xffffffffu, d, o);
        }
        if (l == 0) {
            c = fmaxf(c, 1.0f);   // C1
            d = fmaxf(d, 1.0f);   // C2
            out[0] = (0.5f * (a / d) + 0.5f * (b / c)) * 100.0f;
        }
    }
}

// ---------------------------------------------------------------------------
extern "C" void kernel_launch(void* const* d_in, const int* in_sizes, int n_in,
                              void* d_out, int out_size) {
    const float* a0 = (const float*)d_in[0];
    const float* a1 = (const float*)d_in[1];
    const float* norm;
    const float* pts;
    int n;
    if (in_sizes[0] == 4) { norm = a0; pts = a1; n = in_sizes[1] / 3; }
    else                  { norm = a1; pts = a0; n = in_sizes[0] / 3; }

    float* out = (float*)d_out;

    // init min arrays to "+inf" (0x7F7F7F7F = 3.39e38 > any candidate)
    void* p1 = nullptr; void* p2 = nullptr;
    cudaGetSymbolAddress(&p1, g_d1);
    cudaGetSymbolAddress(&p2, g_d2);
    cudaMemsetAsync(p1, 0x7F, (size_t)n * sizeof(unsigned int), 0);
    cudaMemsetAsync(p2, 0x7F, (size_t)n * sizeof(unsigned int), 0);

    int nt = (n + TILE - 1) / TILE;
    dim3 grid(nt, nt);
    dist_kernel<<<grid, 256>>>(norm, pts, n);

    reduce_kernel<<<1, 1024>>>(norm, pts, out, n);
}

// round 10
// speedup vs baseline: 2.0178x; 1.2767x over previous
#include <cuda_runtime.h>
#include <cuda_bf16.h>

#define NMAX 4096
#define BIGF 1e30f
#define TILE 128
#define DIST_BLOCKS 256

// Scratch (__device__ globals; allocation is forbidden)
__device__ float4 g_rows[NMAX];        // compacted m1: (hx, hy, hz, rr)
__device__ float4 g_cols[NMAX];        // compacted m2: (px, py, pz, -0.5*cc)
__device__ unsigned int g_d1[NMAX];    // per m2-col slot: min over m1 rows (float bits)
__device__ unsigned int g_d2[NMAX];    // per m1-row slot: min over m2 cols (float bits)
__device__ int g_cnt[2];               // {nr, nc}

// ---------------------------------------------------------------------------
// Prep (1 block, 1024 threads): classify, compact (warp-aggregated atomics),
// init min arrays to exactly 1e30 (reference BIG), publish counts.
// ---------------------------------------------------------------------------
__global__ void __launch_bounds__(1024) prep_kernel(const float* __restrict__ norm,
                                                    const float* __restrict__ pts,
                                                    int n) {
    __shared__ int s_nr, s_nc;
    int t = threadIdx.x;
    int lane = t & 31;
    if (t == 0) { s_nr = 0; s_nc = 0; }
    __syncthreads();

    float nx = __ldg(norm), ny = __ldg(norm + 1), nz = __ldg(norm + 2), dd = __ldg(norm + 3);
    float nn = nx * nx + ny * ny + nz * nz;

    int iters = (n + 1023) / 1024;
    for (int k = 0; k < iters; k++) {
        int i = t + k * 1024;
        bool valid = i < n;
        float px = 0.f, py = 0.f, pz = 0.f, ts = 0.f;
        bool m1 = false;
        if (valid) {
            px = pts[3 * i]; py = pts[3 * i + 1]; pz = pts[3 * i + 2];
            ts = -2.0f * (px * nx + py * ny + pz * nz + dd);
            m1 = ts > 0.0f;
            g_d1[i] = __float_as_uint(BIGF);
            g_d2[i] = __float_as_uint(BIGF);
        }
        unsigned lanelt = (1u << lane) - 1u;

        unsigned mk1 = __ballot_sync(0xffffffffu, valid && m1);
        if (mk1) {
            int leader = __ffs(mk1) - 1;
            int base = 0;
            if (lane == leader) base = atomicAdd(&s_nr, __popc(mk1));
            base = __shfl_sync(0xffffffffu, base, leader);
            if (valid && m1) {
                float kk = ts / nn;
                float hx = fmaf(kk, nx, px), hy = fmaf(kk, ny, py), hz = fmaf(kk, nz, pz);
                float rr = fmaf(hx, hx, fmaf(hy, hy, hz * hz));
                g_rows[base + __popc(mk1 & lanelt)] = make_float4(hx, hy, hz, rr);
            }
        }
        unsigned mk2 = __ballot_sync(0xffffffffu, valid && !m1);
        if (mk2) {
            int leader = __ffs(mk2) - 1;
            int base = 0;
            if (lane == leader) base = atomicAdd(&s_nc, __popc(mk2));
            base = __shfl_sync(0xffffffffu, base, leader);
            if (valid && !m1) {
                float cc = fmaf(px, px, fmaf(py, py, pz * pz));
                g_cols[base + __popc(mk2 & lanelt)] = make_float4(px, py, pz, -0.5f * cc);
            }
        }
    }
    __syncthreads();
    if (t == 0) { g_cnt[0] = s_nr; g_cnt[1] = s_nc; }
}

// ---------------------------------------------------------------------------
// Dist: persistent blocks loop over dynamic tile grid (nr x nc compacted).
// 128x128 tile, 256 threads (16x16), 8x8 micro-tile. No masks/penalties:
//   u = dot(r,c) - 0.5*cc;  D = rr - 2u.
//   row min: rr - 2*max_c u;  col min: min_r fma(u,-2,rr).
// => 6 instr/pair (4 FFMA + 2 FMNMX).
// ---------------------------------------------------------------------------
__global__ void __launch_bounds__(256) dist_kernel(int unused) {
    __shared__ float4 srow[TILE];
    __shared__ float4 scol[TILE];
    __shared__ unsigned int credu[TILE];
    __shared__ unsigned int rredu[TILE];

    int t = threadIdx.x;
    int nr = g_cnt[0];
    int nc = g_cnt[1];
    int ntr = (nr + TILE - 1) / TILE;
    int ntc = (nc + TILE - 1) / TILE;
    int ntiles = ntr * ntc;
    int tx = t & 15, ty = t >> 4;

    for (int tile = blockIdx.x; tile < ntiles; tile += DIST_BLOCKS) {
        int by = tile / ntc;
        int bx = tile - by * ntc;
        int i0 = by * TILE;
        int j0 = bx * TILE;

        __syncthreads();                  // protect smem reuse across iterations
        if (t < TILE) {
            int gi = i0 + t;
            srow[t] = (gi < nr) ? g_rows[gi] : make_float4(0.f, 0.f, 0.f, BIGF);
            credu[t] = __float_as_uint(BIGF);
        } else {
            int u = t - TILE;
            int gj = j0 + u;
            scol[u] = (gj < nc) ? g_cols[gj] : make_float4(0.f, 0.f, 0.f, -BIGF);
            rredu[u] = __float_as_uint(BIGF);
        }
        __syncthreads();

        float RX[8], RY[8], RZ[8], RA[8];
#pragma unroll
        for (int r = 0; r < 8; r++) {
            float4 v = srow[ty * 8 + r];
            RX[r] = v.x; RY[r] = v.y; RZ[r] = v.z; RA[r] = v.w;   // rr (or BIG pad)
        }
        float CX[8], CY[8], CZ[8], CI[8];
#pragma unroll
        for (int c = 0; c < 8; c++) {
            float4 v = scol[c * 16 + tx];   // consecutive tx -> conflict-free
            CX[c] = v.x; CY[c] = v.y; CZ[c] = v.z; CI[c] = v.w;   // -0.5cc (or -BIG pad)
        }

        float cmin[8], umax[8];
#pragma unroll
        for (int k = 0; k < 8; k++) { cmin[k] = BIGF; umax[k] = -BIGF; }

#pragma unroll
        for (int r = 0; r < 8; r++) {
            float rxv = RX[r], ryv = RY[r], rzv = RZ[r], Av = RA[r];
            float um = umax[r];
#pragma unroll
            for (int c = 0; c < 8; c++) {
                float u = fmaf(rzv, CZ[c], fmaf(ryv, CY[c], fmaf(rxv, CX[c], CI[c])));
                um      = fmaxf(um, u);
                cmin[c] = fminf(cmin[c], fmaf(u, -2.0f, Av));
            }
            umax[r] = um;
        }

        // block-level combine (clamped >= 0 so uint order == float order)
#pragma unroll
        for (int c = 0; c < 8; c++)
            atomicMin(&credu[c * 16 + tx], __float_as_uint(fmaxf(cmin[c], 0.0f)));
#pragma unroll
        for (int r = 0; r < 8; r++) {
            float v = fmaxf(fmaf(umax[r], -2.0f, RA[r]), 0.0f);   // rr - 2*umax
            atomicMin(&rredu[ty * 8 + r], __float_as_uint(v));
        }
        __syncthreads();

        if (t < TILE) {
            int gj = j0 + t;
            if (gj < nc) atomicMin(&g_d1[gj], credu[t]);
        } else {
            int u = t - TILE;
            int gi = i0 + u;
            if (gi < nr) atomicMin(&g_d2[gi], rredu[u]);
        }
    }
}

// ---------------------------------------------------------------------------
// Reduce: sums over compacted ranges; counts come from g_cnt.
// ---------------------------------------------------------------------------
__global__ void __launch_bounds__(1024) reduce_kernel(float* __restrict__ out) {
    int t = threadIdx.x;
    int nr = g_cnt[0];
    int nc = g_cnt[1];
    int m = nr > nc ? nr : nc;
    float s1 = 0.f, s2 = 0.f;
    for (int i = t; i < m; i += 1024) {
        if (i < nc) s1 += __uint_as_float(g_d1[i]);
        if (i < nr) s2 += __uint_as_float(g_d2[i]);
    }
#pragma unroll
    for (int o = 16; o > 0; o >>= 1) {
        s1 += __shfl_xor_sync(0xffffffffu, s1, o);
        s2 += __shfl_xor_sync(0xffffffffu, s2, o);
    }
    __shared__ float sh[2][32];
    int w = t >> 5, l = t & 31;
    if (l == 0) { sh[0][w] = s1; sh[1][w] = s2; }
    __syncthreads();
    if (w == 0) {
        float a = sh[0][l], b = sh[1][l];
#pragma unroll
        for (int o = 16; o > 0; o >>= 1) {
            a += __shfl_xor_sync(0xffffffffu, a, o);
            b += __shfl_xor_sync(0xffffffffu, b, o);
        }
        if (l == 0) {
            float c2 = fmaxf((float)nc, 1.0f);   // m2 count (av1 divisor)
            float c1 = fmaxf((float)nr, 1.0f);   // m1 count (av2 divisor)
            out[0] = (0.5f * (a / c2) + 0.5f * (b / c1)) * 100.0f;
        }
    }
}

// ---------------------------------------------------------------------------
extern "C" void kernel_launch(void* const* d_in, const int* in_sizes, int n_in,
                              void* d_out, int out_size) {
    const float* a0 = (const float*)d_in[0];
    const float* a1 = (const float*)d_in[1];
    const float* norm;
    const float* pts;
    int n;
    if (in_sizes[0] == 4) { norm = a0; pts = a1; n = in_sizes[1] / 3; }
    else                  { norm = a1; pts = a0; n = in_sizes[0] / 3; }

    float* out = (float*)d_out;

    prep_kernel<<<1, 1024>>>(norm, pts, n);
    dist_kernel<<<DIST_BLOCKS, 256>>>(0);
    reduce_kernel<<<1, 1024>>>(out);
}

// round 11
// speedup vs baseline: 2.5980x; 1.2875x over previous
#include <cuda_runtime.h>
#include <cuda_bf16.h>

#define NMAX 4096
#define BIGF 1e30f
#define TILE 128
#define DIST_BLOCKS 256
#define PREP_THREADS 256

// Scratch (__device__ globals; allocation is forbidden)
__device__ float4 g_rows[NMAX];        // compacted m1: (hx, hy, hz, rr)
__device__ float4 g_cols[NMAX];        // compacted m2: (px, py, pz, -0.5*cc)
__device__ unsigned int g_d1[NMAX];    // per m2-col slot: min over m1 rows (float bits)
__device__ unsigned int g_d2[NMAX];    // per m1-row slot: min over m2 cols (float bits)
__device__ int g_cnt[2] = {0, 0};      // {nr, nc}; reduce_kernel re-zeroes each replay

// ---------------------------------------------------------------------------
// Prep (multi-block): classify, compact via warp-aggregated GLOBAL atomics
// (slot order across blocks is nondeterministic — harmless: all consumers are
// order-invariant min/sum), init min arrays, bump counts.
// ---------------------------------------------------------------------------
__global__ void __launch_bounds__(PREP_THREADS) prep_kernel(const float* __restrict__ norm,
                                                            const float* __restrict__ pts,
                                                            int n) {
    int i = blockIdx.x * PREP_THREADS + threadIdx.x;
    int lane = threadIdx.x & 31;

    float nx = __ldg(norm), ny = __ldg(norm + 1), nz = __ldg(norm + 2), dd = __ldg(norm + 3);
    float nn = nx * nx + ny * ny + nz * nz;

    bool valid = i < n;
    float px = 0.f, py = 0.f, pz = 0.f, ts = 0.f;
    bool m1 = false;
    if (valid) {
        px = pts[3 * i]; py = pts[3 * i + 1]; pz = pts[3 * i + 2];
        ts = -2.0f * (px * nx + py * ny + pz * nz + dd);
        m1 = ts > 0.0f;
        g_d1[i] = __float_as_uint(BIGF);
        g_d2[i] = __float_as_uint(BIGF);
    }
    unsigned lanelt = (1u << lane) - 1u;

    unsigned mk1 = __ballot_sync(0xffffffffu, valid && m1);
    if (mk1) {
        int leader = __ffs(mk1) - 1;
        int base = 0;
        if (lane == leader) base = atomicAdd(&g_cnt[0], __popc(mk1));
        base = __shfl_sync(0xffffffffu, base, leader);
        if (valid && m1) {
            float kk = ts / nn;
            float hx = fmaf(kk, nx, px), hy = fmaf(kk, ny, py), hz = fmaf(kk, nz, pz);
            float rr = fmaf(hx, hx, fmaf(hy, hy, hz * hz));
            g_rows[base + __popc(mk1 & lanelt)] = make_float4(hx, hy, hz, rr);
        }
    }
    unsigned mk2 = __ballot_sync(0xffffffffu, valid && !m1);
    if (mk2) {
        int leader = __ffs(mk2) - 1;
        int base = 0;
        if (lane == leader) base = atomicAdd(&g_cnt[1], __popc(mk2));
        base = __shfl_sync(0xffffffffu, base, leader);
        if (valid && !m1) {
            float cc = fmaf(px, px, fmaf(py, py, pz * pz));
            g_cols[base + __popc(mk2 & lanelt)] = make_float4(px, py, pz, -0.5f * cc);
        }
    }
}

// ---------------------------------------------------------------------------
// Dist: persistent blocks over dynamic tile grid (nr x nc compacted).
// 128x128 tile, 256 threads (16x16), 8x8 micro-tile. No masks/penalties:
//   u = dot(r,c) - 0.5*cc;  D = rr - 2u.
//   row min: rr - 2*max_c u;  col min: min_r fma(u,-2,rr).
// => 6 instr/pair (4 FFMA + 2 FMNMX).
// ---------------------------------------------------------------------------
__global__ void __launch_bounds__(256) dist_kernel(int unused) {
    __shared__ float4 srow[TILE];
    __shared__ float4 scol[TILE];
    __shared__ unsigned int credu[TILE];
    __shared__ unsigned int rredu[TILE];

    int t = threadIdx.x;
    int nr = g_cnt[0];
    int nc = g_cnt[1];
    int ntr = (nr + TILE - 1) / TILE;
    int ntc = (nc + TILE - 1) / TILE;
    int ntiles = ntr * ntc;
    int tx = t & 15, ty = t >> 4;

    for (int tile = blockIdx.x; tile < ntiles; tile += DIST_BLOCKS) {
        int by = tile / ntc;
        int bx = tile - by * ntc;
        int i0 = by * TILE;
        int j0 = bx * TILE;

        __syncthreads();                  // protect smem reuse across iterations
        if (t < TILE) {
            int gi = i0 + t;
            srow[t] = (gi < nr) ? g_rows[gi] : make_float4(0.f, 0.f, 0.f, BIGF);
            credu[t] = __float_as_uint(BIGF);
        } else {
            int u = t - TILE;
            int gj = j0 + u;
            scol[u] = (gj < nc) ? g_cols[gj] : make_float4(0.f, 0.f, 0.f, -BIGF);
            rredu[u] = __float_as_uint(BIGF);
        }
        __syncthreads();

        float RX[8], RY[8], RZ[8], RA[8];
#pragma unroll
        for (int r = 0; r < 8; r++) {
            float4 v = srow[ty * 8 + r];
            RX[r] = v.x; RY[r] = v.y; RZ[r] = v.z; RA[r] = v.w;   // rr (or BIG pad)
        }
        float CX[8], CY[8], CZ[8], CI[8];
#pragma unroll
        for (int c = 0; c < 8; c++) {
            float4 v = scol[c * 16 + tx];   // consecutive tx -> conflict-free
            CX[c] = v.x; CY[c] = v.y; CZ[c] = v.z; CI[c] = v.w;   // -0.5cc (or -BIG pad)
        }

        float cmin[8], umax[8];
#pragma unroll
        for (int k = 0; k < 8; k++) { cmin[k] = BIGF; umax[k] = -BIGF; }

#pragma unroll
        for (int r = 0; r < 8; r++) {
            float rxv = RX[r], ryv = RY[r], rzv = RZ[r], Av = RA[r];
            float um = umax[r];
#pragma unroll
            for (int c = 0; c < 8; c++) {
                float u = fmaf(rzv, CZ[c], fmaf(ryv, CY[c], fmaf(rxv, CX[c], CI[c])));
                um      = fmaxf(um, u);
                cmin[c] = fminf(cmin[c], fmaf(u, -2.0f, Av));
            }
            umax[r] = um;
        }

        // block-level combine (clamped >= 0 so uint order == float order)
#pragma unroll
        for (int c = 0; c < 8; c++)
            atomicMin(&credu[c * 16 + tx], __float_as_uint(fmaxf(cmin[c], 0.0f)));
#pragma unroll
        for (int r = 0; r < 8; r++) {
            float v = fmaxf(fmaf(umax[r], -2.0f, RA[r]), 0.0f);   // rr - 2*umax
            atomicMin(&rredu[ty * 8 + r], __float_as_uint(v));
        }
        __syncthreads();

        if (t < TILE) {
            int gj = j0 + t;
            if (gj < nc) atomicMin(&g_d1[gj], credu[t]);
        } else {
            int u = t - TILE;
            int gi = i0 + u;
            if (gi < nr) atomicMin(&g_d2[gi], rredu[u]);
        }
    }
}

// ---------------------------------------------------------------------------
// Reduce: sums over compacted ranges; zeroes g_cnt for the next graph replay.
// ---------------------------------------------------------------------------
__global__ void __launch_bounds__(1024) reduce_kernel(float* __restrict__ out) {
    int t = threadIdx.x;
    int nr = g_cnt[0];
    int nc = g_cnt[1];
    int m = nr > nc ? nr : nc;
    float s1 = 0.f, s2 = 0.f;
    for (int i = t; i < m; i += 1024) {
        if (i < nc) s1 += __uint_as_float(g_d1[i]);
        if (i < nr) s2 += __uint_as_float(g_d2[i]);
    }
#pragma unroll
    for (int o = 16; o > 0; o >>= 1) {
        s1 += __shfl_xor_sync(0xffffffffu, s1, o);
        s2 += __shfl_xor_sync(0xffffffffu, s2, o);
    }
    __shared__ float sh[2][32];
    int w = t >> 5, l = t & 31;
    if (l == 0) { sh[0][w] = s1; sh[1][w] = s2; }
    __syncthreads();
    if (t == 0) { g_cnt[0] = 0; g_cnt[1] = 0; }   // restore pre-replay state
    if (w == 0) {
        float a = sh[0][l], b = sh[1][l];
#pragma unroll
        for (int o = 16; o > 0; o >>= 1) {
            a += __shfl_xor_sync(0xffffffffu, a, o);
            b += __shfl_xor_sync(0xffffffffu, b, o);
        }
        if (l == 0) {
            float c2 = fmaxf((float)nc, 1.0f);   // m2 count (av1 divisor)
            float c1 = fmaxf((float)nr, 1.0f);   // m1 count (av2 divisor)
            out[0] = (0.5f * (a / c2) + 0.5f * (b / c1)) * 100.0f;
        }
    }
}

// ---------------------------------------------------------------------------
extern "C" void kernel_launch(void* const* d_in, const int* in_sizes, int n_in,
                              void* d_out, int out_size) {
    const float* a0 = (const float*)d_in[0];
    const float* a1 = (const float*)d_in[1];
    const float* norm;
    const float* pts;
    int n;
    if (in_sizes[0] == 4) { norm = a0; pts = a1; n = in_sizes[1] / 3; }
    else                  { norm = a1; pts = a0; n = in_sizes[0] / 3; }

    float* out = (float*)d_out;

    int pb = (n + PREP_THREADS - 1) / PREP_THREADS;
    prep_kernel<<<pb, PREP_THREADS>>>(norm, pts, n);
    dist_kernel<<<DIST_BLOCKS, 256>>>(0);
    reduce_kernel<<<1, 1024>>>(out);
}